// round 1
// baseline (speedup 1.0000x reference)
#include <cuda_runtime.h>
#include <math.h>
#include <stdint.h>

#define NMAX 100000
#define EMAX 1000000
#define GMAXG 512

// ---------------- scratch (device globals; no allocation allowed) ----------------
__device__ float g_h[NMAX * 64];          // current node features (residual stream)
__device__ float g_t[NMAX * 64];          // attn accumulator / pre-BN buffer
__device__ float g_q[NMAX * 64];
__device__ float g_k[NMAX * 64];
__device__ float g_v[NMAX * 64];
__device__ float g_skip[NMAX * 64];
__device__ float g_e[(size_t)EMAX * 64];  // per-edge projected edge features
__device__ float g_alpha[EMAX * 4];
__device__ float g_amax[NMAX * 4];
__device__ float g_denom[NMAX * 4];
__device__ float g_bnsum[64];
__device__ float g_bnsq[64];
__device__ float g_pool[GMAXG * 64];
__device__ float g_cnt[GMAXG];

static inline unsigned divup(long long a, int b) { return (unsigned)((a + b - 1) / b); }

// ---------------- generic node/edge linear: out[n,64] = in[n,K] @ W[K,64] + b ----------------
template <int K>
__global__ void lin_kernel(const float* __restrict__ in, const float* __restrict__ W,
                           const float* __restrict__ bias, float* __restrict__ out, int n) {
    __shared__ float sW[K * 64];
    __shared__ float sb[64];
    for (int i = threadIdx.x; i < K * 64; i += blockDim.x) sW[i] = W[i];
    if (threadIdx.x < 64) sb[threadIdx.x] = bias[threadIdx.x];
    __syncthreads();
    int node = blockIdx.x * blockDim.x + threadIdx.x;
    if (node >= n) return;

    float4 acc[16];
#pragma unroll
    for (int j = 0; j < 16; j++) {
        acc[j].x = sb[4 * j + 0]; acc[j].y = sb[4 * j + 1];
        acc[j].z = sb[4 * j + 2]; acc[j].w = sb[4 * j + 3];
    }
    const float4* inp = reinterpret_cast<const float4*>(in + (size_t)node * K);
#pragma unroll
    for (int c = 0; c < K / 4; c++) {
        float4 x4 = inp[c];
        float xs[4] = {x4.x, x4.y, x4.z, x4.w};
#pragma unroll
        for (int kk = 0; kk < 4; kk++) {
            float x = xs[kk];
            const float4* wr = reinterpret_cast<const float4*>(&sW[(c * 4 + kk) * 64]);
#pragma unroll
            for (int j = 0; j < 16; j++) {
                float4 w = wr[j];
                acc[j].x += x * w.x; acc[j].y += x * w.y;
                acc[j].z += x * w.z; acc[j].w += x * w.w;
            }
        }
    }
    float4* op = reinterpret_cast<float4*>(out + (size_t)node * 64);
#pragma unroll
    for (int j = 0; j < 16; j++) op[j] = acc[j];
}

// ---------------- per-layer scratch clear ----------------
__global__ void clear_layer_kernel(int n) {
    int i = blockIdx.x * blockDim.x + threadIdx.x;
    int n64 = n * 64;
    if (i < n64) g_t[i] = 0.0f;
    if (i < n * 4) {
        g_denom[i] = 0.0f;
        g_amax[i] = __int_as_float(0xff800000);  // -inf
    }
    if (i < 64) { g_bnsum[i] = 0.0f; g_bnsq[i] = 0.0f; }
}

__device__ __forceinline__ void atomicMaxFloat(float* addr, float val) {
    if (val >= 0.0f) atomicMax((int*)addr, __float_as_int(val));
    else             atomicMin((unsigned int*)addr, __float_as_uint(val));
}

// ---------------- edge pass 1: alpha + segment max ----------------
__global__ void edge_pass1_kernel(const int* __restrict__ ei, int e) {
    int idx = blockIdx.x * blockDim.x + threadIdx.x;
    if (idx >= e * 4) return;
    int eid = idx >> 2, hh = idx & 3;
    int src = ei[eid];
    int dst = ei[e + eid];
    const float4* qp = reinterpret_cast<const float4*>(g_q + (size_t)dst * 64 + hh * 16);
    const float4* kp = reinterpret_cast<const float4*>(g_k + (size_t)src * 64 + hh * 16);
    const float4* ep = reinterpret_cast<const float4*>(g_e + (size_t)eid * 64 + hh * 16);
    float a = 0.0f;
#pragma unroll
    for (int i = 0; i < 4; i++) {
        float4 q = qp[i], k = kp[i], ee = ep[i];
        a += q.x * (k.x + ee.x) + q.y * (k.y + ee.y) + q.z * (k.z + ee.z) + q.w * (k.w + ee.w);
    }
    a *= 0.25f;  // 1/sqrt(16)
    g_alpha[idx] = a;
    atomicMaxFloat(&g_amax[dst * 4 + hh], a);
}

// ---------------- edge pass 2: exp, denom, unnormalized weighted scatter-sum ----------------
__global__ void edge_pass2_kernel(const int* __restrict__ ei, int e) {
    int idx = blockIdx.x * blockDim.x + threadIdx.x;
    if (idx >= e * 4) return;
    int eid = idx >> 2, hh = idx & 3;
    int src = ei[eid];
    int dst = ei[e + eid];
    float a = g_alpha[idx];
    float m = g_amax[dst * 4 + hh];
    float ex = expf(a - m);
    atomicAdd(&g_denom[dst * 4 + hh], ex);
    const float4* vp = reinterpret_cast<const float4*>(g_v + (size_t)src * 64 + hh * 16);
    const float4* ep = reinterpret_cast<const float4*>(g_e + (size_t)eid * 64 + hh * 16);
    float* ob = g_t + (size_t)dst * 64 + hh * 16;
#pragma unroll
    for (int i = 0; i < 4; i++) {
        float4 v = vp[i], ee = ep[i];
        atomicAdd(ob + i * 4 + 0, ex * (v.x + ee.x));
        atomicAdd(ob + i * 4 + 1, ex * (v.y + ee.y));
        atomicAdd(ob + i * 4 + 2, ex * (v.z + ee.z));
        atomicAdd(ob + i * 4 + 3, ex * (v.w + ee.w));
    }
}

// ---------------- finalize attention: t = t/(denom+1e-16) + skip ----------------
__global__ void finalize_attn_kernel(int n) {
    int idx = blockIdx.x * blockDim.x + threadIdx.x;  // (node, head)
    if (idx >= n * 4) return;
    int node = idx >> 2, hh = idx & 3;
    float inv = 1.0f / (g_denom[idx] + 1e-16f);
    float4* tp = reinterpret_cast<float4*>(g_t + (size_t)node * 64 + hh * 16);
    const float4* sp = reinterpret_cast<const float4*>(g_skip + (size_t)node * 64 + hh * 16);
#pragma unroll
    for (int i = 0; i < 4; i++) {
        float4 t = tp[i], s = sp[i];
        t.x = t.x * inv + s.x; t.y = t.y * inv + s.y;
        t.z = t.z * inv + s.z; t.w = t.w * inv + s.w;
        tp[i] = t;
    }
}

// ---------------- BN stats: per-channel sum and sumsq over g_t ----------------
__global__ void bn_stats_kernel(int n) {
    int tid = threadIdx.x;
    int c = tid & 63;
    int rowg = tid >> 6;  // 0..3
    float s = 0.0f, q = 0.0f;
    for (int r = blockIdx.x * 4 + rowg; r < n; r += gridDim.x * 4) {
        float v = g_t[(size_t)r * 64 + c];
        s += v; q += v * v;
    }
    __shared__ float ss[256], sq[256];
    ss[tid] = s; sq[tid] = q;
    __syncthreads();
    if (tid < 128) { ss[tid] += ss[tid + 128]; sq[tid] += sq[tid + 128]; }
    __syncthreads();
    if (tid < 64) {
        atomicAdd(&g_bnsum[tid], ss[tid] + ss[tid + 64]);
        atomicAdd(&g_bnsq[tid], sq[tid] + sq[tid + 64]);
    }
}

// ---------------- BN apply + GELU + residual: h = gelu(bn(t)) + h ----------------
__global__ void bn_apply_kernel(const float* __restrict__ gamma, const float* __restrict__ beta, int n) {
    int idx = blockIdx.x * blockDim.x + threadIdx.x;  // float4 index over n*16
    if (idx >= n * 16) return;
    int c0 = (idx & 15) * 4;
    float invN = 1.0f / (float)n;
    float4 tv = reinterpret_cast<const float4*>(g_t)[idx];
    float4 hv = reinterpret_cast<const float4*>(g_h)[idx];
    float tt[4] = {tv.x, tv.y, tv.z, tv.w};
    float hh[4] = {hv.x, hv.y, hv.z, hv.w};
    float r[4];
#pragma unroll
    for (int k = 0; k < 4; k++) {
        int c = c0 + k;
        float mu = g_bnsum[c] * invN;
        float var = g_bnsq[c] * invN - mu * mu;
        float y = gamma[c] * (tt[k] - mu) * rsqrtf(var + 1e-5f) + beta[c];
        float gl = 0.5f * y * (1.0f + erff(y * 0.70710678118654752f));
        r[k] = gl + hh[k];
    }
    float4 o; o.x = r[0]; o.y = r[1]; o.z = r[2]; o.w = r[3];
    reinterpret_cast<float4*>(g_h)[idx] = o;
}

// ---------------- pooling ----------------
__global__ void clear_pool_kernel(int G) {
    int i = blockIdx.x * blockDim.x + threadIdx.x;
    if (i < G * 64) g_pool[i] = 0.0f;
    if (i < G) g_cnt[i] = 0.0f;
}

__global__ void pool_kernel(const int* __restrict__ batch, int n) {
    int idx = blockIdx.x * blockDim.x + threadIdx.x;
    if (idx >= n * 64) return;
    int node = idx >> 6, c = idx & 63;
    int g = batch[node];
    atomicAdd(&g_pool[g * 64 + c], g_h[idx]);
    if (c == 0) atomicAdd(&g_cnt[g], 1.0f);
}

// ---------------- regressor: out[g] = relu([mean||sum] @ rw1 + rb1) @ rw2 + rb2 ----------------
__global__ void reg_kernel(const float* __restrict__ rw1, const float* __restrict__ rb1,
                           const float* __restrict__ rw2, const float* __restrict__ rb2,
                           float* __restrict__ out) {
    int g = blockIdx.x;
    int tid = threadIdx.x;  // 128 threads
    __shared__ float feat[128];
    __shared__ float hred[64];
    float invc = 1.0f / fmaxf(g_cnt[g], 1.0f);
    float s = g_pool[g * 64 + (tid & 63)];
    feat[tid] = (tid < 64) ? s * invc : s;
    __syncthreads();
    if (tid < 64) {
        float acc = rb1[tid];
#pragma unroll 8
        for (int i = 0; i < 128; i++) acc += feat[i] * rw1[i * 64 + tid];
        acc = fmaxf(acc, 0.0f);
        hred[tid] = acc * rw2[tid];
    }
    __syncthreads();
    if (tid < 32) {
        float v = hred[tid] + hred[tid + 32];
#pragma unroll
        for (int off = 16; off > 0; off >>= 1) v += __shfl_down_sync(0xffffffffu, v, off);
        if (tid == 0) out[g] = v + rb2[0];
    }
}

// ---------------- host orchestration ----------------
extern "C" void kernel_launch(void* const* d_in, const int* in_sizes, int n_in,
                              void* d_out, int out_size) {
    const float* x      = (const float*)d_in[0];
    const int*   ei     = (const int*)d_in[1];
    const float* eattr  = (const float*)d_in[2];
    const int*   batch  = (const int*)d_in[3];
    const float* node_w = (const float*)d_in[4];
    const float* node_b = (const float*)d_in[5];
    const float* Wq = (const float*)d_in[6];
    const float* bq = (const float*)d_in[7];
    const float* Wk = (const float*)d_in[8];
    const float* bk = (const float*)d_in[9];
    const float* Wv = (const float*)d_in[10];
    const float* bv = (const float*)d_in[11];
    const float* We = (const float*)d_in[12];
    const float* be = (const float*)d_in[13];
    const float* Ws = (const float*)d_in[14];
    const float* bs = (const float*)d_in[15];
    const float* gamma = (const float*)d_in[16];
    const float* beta  = (const float*)d_in[17];
    const float* rw1 = (const float*)d_in[18];
    const float* rb1 = (const float*)d_in[19];
    const float* rw2 = (const float*)d_in[20];
    const float* rb2 = (const float*)d_in[21];
    float* out = (float*)d_out;

    int n = in_sizes[0] / 32;   // nodes
    int e = in_sizes[2] / 16;   // edges
    int G = out_size;           // graphs

    float *ph, *pq, *pk, *pv, *ps, *pe;
    cudaGetSymbolAddress((void**)&ph, g_h);
    cudaGetSymbolAddress((void**)&pq, g_q);
    cudaGetSymbolAddress((void**)&pk, g_k);
    cudaGetSymbolAddress((void**)&pv, g_v);
    cudaGetSymbolAddress((void**)&ps, g_skip);
    cudaGetSymbolAddress((void**)&pe, g_e);

    // h0 = x @ node_w + node_b
    lin_kernel<32><<<divup(n, 128), 128>>>(x, node_w, node_b, ph, n);

    for (int l = 0; l < 3; l++) {
        const float* wq = Wq + (size_t)l * 64 * 64;
        const float* wk = Wk + (size_t)l * 64 * 64;
        const float* wv = Wv + (size_t)l * 64 * 64;
        const float* ws = Ws + (size_t)l * 64 * 64;
        const float* we = We + (size_t)l * 16 * 64;

        lin_kernel<64><<<divup(n, 128), 128>>>(ph, wq, bq + l * 64, pq, n);
        lin_kernel<64><<<divup(n, 128), 128>>>(ph, wk, bk + l * 64, pk, n);
        lin_kernel<64><<<divup(n, 128), 128>>>(ph, wv, bv + l * 64, pv, n);
        lin_kernel<64><<<divup(n, 128), 128>>>(ph, ws, bs + l * 64, ps, n);
        lin_kernel<16><<<divup(e, 128), 128>>>(eattr, we, be + l * 64, pe, e);

        clear_layer_kernel<<<divup((long long)n * 64, 256), 256>>>(n);
        edge_pass1_kernel<<<divup((long long)e * 4, 256), 256>>>(ei, e);
        edge_pass2_kernel<<<divup((long long)e * 4, 256), 256>>>(ei, e);
        finalize_attn_kernel<<<divup((long long)n * 4, 256), 256>>>(n);
        bn_stats_kernel<<<2048, 256>>>(n);
        bn_apply_kernel<<<divup((long long)n * 16, 256), 256>>>(gamma + l * 64, beta + l * 64, n);
    }

    clear_pool_kernel<<<divup((long long)G * 64, 256), 256>>>(G);
    pool_kernel<<<divup((long long)n * 64, 256), 256>>>(batch, n);
    reg_kernel<<<G, 128>>>(rw1, rb1, rw2, rb2, out);
}

// round 3
// speedup vs baseline: 1.0005x; 1.0005x over previous
#include <cuda_runtime.h>
#include <math.h>
#include <stdint.h>

#define NMAX 100000
#define EMAX 1000000
#define GMAXG 512

// ---------------- scratch (device globals; no allocation allowed) ----------------
__device__ float g_h[NMAX * 64];          // current node features (residual stream)
__device__ float g_t[NMAX * 64];          // attn accumulator / pre-BN buffer
__device__ float g_q[NMAX * 64];
__device__ float g_k[NMAX * 64];
__device__ float g_v[NMAX * 64];
__device__ float g_skip[NMAX * 64];
__device__ float g_alpha[EMAX * 4];
__device__ float g_amax[NMAX * 4];
__device__ float g_denom[NMAX * 4];
__device__ float g_bnsum[64];
__device__ float g_bnsq[64];
__device__ float g_pool[GMAXG * 64];
__device__ float g_cnt[GMAXG];

static inline unsigned divup(long long a, int b) { return (unsigned)((a + b - 1) / b); }

__device__ __forceinline__ void redAddV4(float* addr, float a, float b, float c, float d) {
    asm volatile("red.global.add.v4.f32 [%0], {%1,%2,%3,%4};"
                 :: "l"(addr), "f"(a), "f"(b), "f"(c), "f"(d) : "memory");
}

__device__ __forceinline__ void atomicMaxFloat(float* addr, float val) {
    if (val >= 0.0f) atomicMax((int*)addr, __float_as_int(val));
    else             atomicMin((unsigned int*)addr, __float_as_uint(val));
}

// ---------------- initial node linear: out[n,64] = in[n,32] @ W[32,64] + b ----------------
__global__ void lin32_kernel(const float* __restrict__ in, const float* __restrict__ W,
                             const float* __restrict__ bias, float* __restrict__ out, int n) {
    __shared__ float sW[32 * 64];
    __shared__ float sb[64];
    for (int i = threadIdx.x; i < 32 * 64; i += blockDim.x) sW[i] = W[i];
    if (threadIdx.x < 64) sb[threadIdx.x] = bias[threadIdx.x];
    __syncthreads();
    int node = blockIdx.x * blockDim.x + threadIdx.x;
    if (node >= n) return;
    float4 acc[16];
#pragma unroll
    for (int j = 0; j < 16; j++) {
        acc[j].x = sb[4 * j + 0]; acc[j].y = sb[4 * j + 1];
        acc[j].z = sb[4 * j + 2]; acc[j].w = sb[4 * j + 3];
    }
    const float4* inp = reinterpret_cast<const float4*>(in + (size_t)node * 32);
#pragma unroll
    for (int c = 0; c < 8; c++) {
        float4 x4 = inp[c];
        float xs[4] = {x4.x, x4.y, x4.z, x4.w};
#pragma unroll
        for (int kk = 0; kk < 4; kk++) {
            float x = xs[kk];
            const float4* wr = reinterpret_cast<const float4*>(&sW[(c * 4 + kk) * 64]);
#pragma unroll
            for (int j = 0; j < 16; j++) {
                float4 w = wr[j];
                acc[j].x += x * w.x; acc[j].y += x * w.y;
                acc[j].z += x * w.z; acc[j].w += x * w.w;
            }
        }
    }
    float4* op = reinterpret_cast<float4*>(out + (size_t)node * 64);
#pragma unroll
    for (int j = 0; j < 16; j++) op[j] = acc[j];
}

// ---------------- fused q/k/v/skip: 4x (h @ W + b), h tile staged in smem ----------------
// block = 256 threads = 64 nodes x 4 column-quarters (16 cols each)
__global__ void qkvs_kernel(const float* __restrict__ h,
                            const float* __restrict__ Wq, const float* __restrict__ bq,
                            const float* __restrict__ Wk, const float* __restrict__ bk,
                            const float* __restrict__ Wv, const float* __restrict__ bv,
                            const float* __restrict__ Ws, const float* __restrict__ bs,
                            float* __restrict__ oq, float* __restrict__ ok,
                            float* __restrict__ ov, float* __restrict__ os, int n) {
    __shared__ float xs[64 * 65];          // 16640 B (padded, conflict-free broadcast)
    __shared__ float sW[64 * 64];          // 16384 B
    __shared__ float sb[64];
    const int tid = threadIdx.x;
    const int base = blockIdx.x * 64;

    // stage input tile
    for (int idx = tid; idx < 64 * 16; idx += 256) {
        int nl = idx >> 4, kk = idx & 15;
        int gn = base + nl;
        if (gn < n) {
            float4 x4 = reinterpret_cast<const float4*>(h + (size_t)gn * 64)[kk];
            float* p = &xs[nl * 65 + kk * 4];
            p[0] = x4.x; p[1] = x4.y; p[2] = x4.z; p[3] = x4.w;
        }
    }

    const float* Wm[4] = {Wq, Wk, Wv, Ws};
    const float* bm[4] = {bq, bk, bv, bs};
    float* om[4] = {oq, ok, ov, os};

    const int nl = tid & 63;
    const int quart = tid >> 6;           // 0..3 -> cols [quart*16, quart*16+16)
    const int gn = base + nl;

#pragma unroll
    for (int m = 0; m < 4; m++) {
        __syncthreads();
        {
            const float4* wsrc = reinterpret_cast<const float4*>(Wm[m]);
            float4* wdst = reinterpret_cast<float4*>(sW);
            for (int i = tid; i < 1024; i += 256) wdst[i] = wsrc[i];
            if (tid < 64) sb[tid] = bm[m][tid];
        }
        __syncthreads();
        if (gn < n) {
            float4 acc[4];
#pragma unroll
            for (int j = 0; j < 4; j++) {
                acc[j].x = sb[quart * 16 + 4 * j + 0];
                acc[j].y = sb[quart * 16 + 4 * j + 1];
                acc[j].z = sb[quart * 16 + 4 * j + 2];
                acc[j].w = sb[quart * 16 + 4 * j + 3];
            }
            const float* xrow = &xs[nl * 65];
#pragma unroll 8
            for (int k = 0; k < 64; k++) {
                float x = xrow[k];
                const float4* wr = reinterpret_cast<const float4*>(&sW[k * 64 + quart * 16]);
#pragma unroll
                for (int j = 0; j < 4; j++) {
                    float4 w = wr[j];
                    acc[j].x += x * w.x; acc[j].y += x * w.y;
                    acc[j].z += x * w.z; acc[j].w += x * w.w;
                }
            }
            float4* op = reinterpret_cast<float4*>(om[m] + (size_t)gn * 64 + quart * 16);
#pragma unroll
            for (int j = 0; j < 4; j++) op[j] = acc[j];
        }
    }
}

// ---------------- per-layer scratch clear ----------------
__global__ void clear_layer_kernel(int n) {
    int i = blockIdx.x * blockDim.x + threadIdx.x;
    int n64 = n * 64;
    if (i < n64) g_t[i] = 0.0f;
    if (i < n * 4) {
        g_denom[i] = 0.0f;
        g_amax[i] = __int_as_float(0xff800000);  // -inf
    }
    if (i < 64) { g_bnsum[i] = 0.0f; g_bnsq[i] = 0.0f; }
}

// ---------------- edge pass 1: fused e-proj + alpha + segment max ----------------
__global__ void edge_pass1_kernel(const int* __restrict__ ei, const float* __restrict__ eattr,
                                  const float* __restrict__ We, const float* __restrict__ be, int e) {
    __shared__ float sWe[16 * 64];
    __shared__ float sbe[64];
    const int tid = threadIdx.x;
    for (int i = tid; i < 1024; i += 256) sWe[i] = We[i];
    if (tid < 64) sbe[tid] = be[tid];
    __syncthreads();

    int idx = blockIdx.x * 256 + tid;
    if (idx >= e * 4) return;
    int eid = idx >> 2, hh = idx & 3;
    int src = ei[eid];
    int dst = ei[e + eid];

    // e projection for this head's 16 columns
    float4 ev[4];
#pragma unroll
    for (int j = 0; j < 4; j++) {
        ev[j].x = sbe[hh * 16 + 4 * j + 0]; ev[j].y = sbe[hh * 16 + 4 * j + 1];
        ev[j].z = sbe[hh * 16 + 4 * j + 2]; ev[j].w = sbe[hh * 16 + 4 * j + 3];
    }
    const float4* ea = reinterpret_cast<const float4*>(eattr + (size_t)eid * 16);
#pragma unroll
    for (int c = 0; c < 4; c++) {
        float4 x4 = ea[c];
        float xsv[4] = {x4.x, x4.y, x4.z, x4.w};
#pragma unroll
        for (int kk = 0; kk < 4; kk++) {
            float x = xsv[kk];
            const float4* wr = reinterpret_cast<const float4*>(&sWe[(c * 4 + kk) * 64 + hh * 16]);
#pragma unroll
            for (int j = 0; j < 4; j++) {
                float4 w = wr[j];
                ev[j].x += x * w.x; ev[j].y += x * w.y;
                ev[j].z += x * w.z; ev[j].w += x * w.w;
            }
        }
    }

    const float4* qp = reinterpret_cast<const float4*>(g_q + (size_t)dst * 64 + hh * 16);
    const float4* kp = reinterpret_cast<const float4*>(g_k + (size_t)src * 64 + hh * 16);
    float a = 0.0f;
#pragma unroll
    for (int i = 0; i < 4; i++) {
        float4 q = qp[i], k = kp[i];
        a += q.x * (k.x + ev[i].x) + q.y * (k.y + ev[i].y)
           + q.z * (k.z + ev[i].z) + q.w * (k.w + ev[i].w);
    }
    a *= 0.25f;  // 1/sqrt(16)
    g_alpha[idx] = a;
    atomicMaxFloat(&g_amax[dst * 4 + hh], a);
}

// ---------------- edge pass 2: fused e-proj + exp + vector scatter-add ----------------
__global__ void edge_pass2_kernel(const int* __restrict__ ei, const float* __restrict__ eattr,
                                  const float* __restrict__ We, const float* __restrict__ be, int e) {
    __shared__ float sWe[16 * 64];
    __shared__ float sbe[64];
    const int tid = threadIdx.x;
    for (int i = tid; i < 1024; i += 256) sWe[i] = We[i];
    if (tid < 64) sbe[tid] = be[tid];
    __syncthreads();

    int idx = blockIdx.x * 256 + tid;
    if (idx >= e * 4) return;
    int eid = idx >> 2, hh = idx & 3;
    int src = ei[eid];
    int dst = ei[e + eid];

    float a = g_alpha[idx];
    float m = g_amax[dst * 4 + hh];
    float ex = expf(a - m);
    atomicAdd(&g_denom[dst * 4 + hh], ex);  // compiles to RED (no return use)

    float4 ev[4];
#pragma unroll
    for (int j = 0; j < 4; j++) {
        ev[j].x = sbe[hh * 16 + 4 * j + 0]; ev[j].y = sbe[hh * 16 + 4 * j + 1];
        ev[j].z = sbe[hh * 16 + 4 * j + 2]; ev[j].w = sbe[hh * 16 + 4 * j + 3];
    }
    const float4* ea = reinterpret_cast<const float4*>(eattr + (size_t)eid * 16);
#pragma unroll
    for (int c = 0; c < 4; c++) {
        float4 x4 = ea[c];
        float xsv[4] = {x4.x, x4.y, x4.z, x4.w};
#pragma unroll
        for (int kk = 0; kk < 4; kk++) {
            float x = xsv[kk];
            const float4* wr = reinterpret_cast<const float4*>(&sWe[(c * 4 + kk) * 64 + hh * 16]);
#pragma unroll
            for (int j = 0; j < 4; j++) {
                float4 w = wr[j];
                ev[j].x += x * w.x; ev[j].y += x * w.y;
                ev[j].z += x * w.z; ev[j].w += x * w.w;
            }
        }
    }

    const float4* vp = reinterpret_cast<const float4*>(g_v + (size_t)src * 64 + hh * 16);
    float* ob = g_t + (size_t)dst * 64 + hh * 16;
#pragma unroll
    for (int i = 0; i < 4; i++) {
        float4 v = vp[i];
        redAddV4(ob + i * 4, ex * (v.x + ev[i].x), ex * (v.y + ev[i].y),
                             ex * (v.z + ev[i].z), ex * (v.w + ev[i].w));
    }
}

// ---------------- finalize attention: t = t/(denom+1e-16) + skip ----------------
__global__ void finalize_attn_kernel(int n) {
    int idx = blockIdx.x * blockDim.x + threadIdx.x;  // (node, head)
    if (idx >= n * 4) return;
    int node = idx >> 2, hh = idx & 3;
    float inv = 1.0f / (g_denom[idx] + 1e-16f);
    float4* tp = reinterpret_cast<float4*>(g_t + (size_t)node * 64 + hh * 16);
    const float4* sp = reinterpret_cast<const float4*>(g_skip + (size_t)node * 64 + hh * 16);
#pragma unroll
    for (int i = 0; i < 4; i++) {
        float4 t = tp[i], s = sp[i];
        t.x = t.x * inv + s.x; t.y = t.y * inv + s.y;
        t.z = t.z * inv + s.z; t.w = t.w * inv + s.w;
        tp[i] = t;
    }
}

// ---------------- BN stats ----------------
__global__ void bn_stats_kernel(int n) {
    int tid = threadIdx.x;
    int c = tid & 63;
    int rowg = tid >> 6;
    float s = 0.0f, q = 0.0f;
    for (int r = blockIdx.x * 4 + rowg; r < n; r += gridDim.x * 4) {
        float v = g_t[(size_t)r * 64 + c];
        s += v; q += v * v;
    }
    __shared__ float ss[256], sq[256];
    ss[tid] = s; sq[tid] = q;
    __syncthreads();
    if (tid < 128) { ss[tid] += ss[tid + 128]; sq[tid] += sq[tid + 128]; }
    __syncthreads();
    if (tid < 64) {
        atomicAdd(&g_bnsum[tid], ss[tid] + ss[tid + 64]);
        atomicAdd(&g_bnsq[tid], sq[tid] + sq[tid + 64]);
    }
}

// ---------------- BN apply + GELU + residual ----------------
__global__ void bn_apply_kernel(const float* __restrict__ gamma, const float* __restrict__ beta, int n) {
    int idx = blockIdx.x * blockDim.x + threadIdx.x;
    if (idx >= n * 16) return;
    int c0 = (idx & 15) * 4;
    float invN = 1.0f / (float)n;
    float4 tv = reinterpret_cast<const float4*>(g_t)[idx];
    float4 hv = reinterpret_cast<const float4*>(g_h)[idx];
    float tt[4] = {tv.x, tv.y, tv.z, tv.w};
    float hh[4] = {hv.x, hv.y, hv.z, hv.w};
    float r[4];
#pragma unroll
    for (int k = 0; k < 4; k++) {
        int c = c0 + k;
        float mu = g_bnsum[c] * invN;
        float var = g_bnsq[c] * invN - mu * mu;
        float y = gamma[c] * (tt[k] - mu) * rsqrtf(var + 1e-5f) + beta[c];
        float gl = 0.5f * y * (1.0f + erff(y * 0.70710678118654752f));
        r[k] = gl + hh[k];
    }
    float4 o; o.x = r[0]; o.y = r[1]; o.z = r[2]; o.w = r[3];
    reinterpret_cast<float4*>(g_h)[idx] = o;
}

// ---------------- pooling ----------------
__global__ void clear_pool_kernel(int G) {
    int i = blockIdx.x * blockDim.x + threadIdx.x;
    if (i < G * 64) g_pool[i] = 0.0f;
    if (i < G) g_cnt[i] = 0.0f;
}

__global__ void pool_kernel(const int* __restrict__ batch, int n) {
    int idx = blockIdx.x * blockDim.x + threadIdx.x;  // float4 groups: n*16
    if (idx >= n * 16) return;
    int node = idx >> 4, c4 = idx & 15;
    int g = batch[node];
    float4 v = reinterpret_cast<const float4*>(g_h)[idx];
    redAddV4(&g_pool[g * 64 + c4 * 4], v.x, v.y, v.z, v.w);
    if (c4 == 0) atomicAdd(&g_cnt[g], 1.0f);
}

// ---------------- regressor ----------------
__global__ void reg_kernel(const float* __restrict__ rw1, const float* __restrict__ rb1,
                           const float* __restrict__ rw2, const float* __restrict__ rb2,
                           float* __restrict__ out) {
    int g = blockIdx.x;
    int tid = threadIdx.x;  // 128 threads
    __shared__ float feat[128];
    __shared__ float hred[64];
    float invc = 1.0f / fmaxf(g_cnt[g], 1.0f);
    float s = g_pool[g * 64 + (tid & 63)];
    feat[tid] = (tid < 64) ? s * invc : s;
    __syncthreads();
    if (tid < 64) {
        float acc = rb1[tid];
#pragma unroll 8
        for (int i = 0; i < 128; i++) acc += feat[i] * rw1[i * 64 + tid];
        acc = fmaxf(acc, 0.0f);
        hred[tid] = acc * rw2[tid];
    }
    __syncthreads();
    if (tid < 32) {
        float v = hred[tid] + hred[tid + 32];
#pragma unroll
        for (int off = 16; off > 0; off >>= 1) v += __shfl_down_sync(0xffffffffu, v, off);
        if (tid == 0) out[g] = v + rb2[0];
    }
}

// ---------------- host orchestration ----------------
extern "C" void kernel_launch(void* const* d_in, const int* in_sizes, int n_in,
                              void* d_out, int out_size) {
    const float* x      = (const float*)d_in[0];
    const int*   ei     = (const int*)d_in[1];
    const float* eattr  = (const float*)d_in[2];
    const int*   batch  = (const int*)d_in[3];
    const float* node_w = (const float*)d_in[4];
    const float* node_b = (const float*)d_in[5];
    const float* Wq = (const float*)d_in[6];
    const float* bq = (const float*)d_in[7];
    const float* Wk = (const float*)d_in[8];
    const float* bk = (const float*)d_in[9];
    const float* Wv = (const float*)d_in[10];
    const float* bv = (const float*)d_in[11];
    const float* We = (const float*)d_in[12];
    const float* be = (const float*)d_in[13];
    const float* Ws = (const float*)d_in[14];
    const float* bs = (const float*)d_in[15];
    const float* gamma = (const float*)d_in[16];
    const float* beta  = (const float*)d_in[17];
    const float* rw1 = (const float*)d_in[18];
    const float* rb1 = (const float*)d_in[19];
    const float* rw2 = (const float*)d_in[20];
    const float* rb2 = (const float*)d_in[21];
    float* out = (float*)d_out;

    int n = in_sizes[0] / 32;   // nodes
    int e = in_sizes[2] / 16;   // edges
    int G = out_size;           // graphs

    float *ph, *pq, *pk, *pv, *ps;
    cudaGetSymbolAddress((void**)&ph, g_h);
    cudaGetSymbolAddress((void**)&pq, g_q);
    cudaGetSymbolAddress((void**)&pk, g_k);
    cudaGetSymbolAddress((void**)&pv, g_v);
    cudaGetSymbolAddress((void**)&ps, g_skip);

    lin32_kernel<<<divup(n, 128), 128>>>(x, node_w, node_b, ph, n);

    for (int l = 0; l < 3; l++) {
        const float* wq = Wq + (size_t)l * 64 * 64;
        const float* wk = Wk + (size_t)l * 64 * 64;
        const float* wv = Wv + (size_t)l * 64 * 64;
        const float* ws = Ws + (size_t)l * 64 * 64;
        const float* we = We + (size_t)l * 16 * 64;

        qkvs_kernel<<<divup(n, 64), 256>>>(ph, wq, bq + l * 64, wk, bk + l * 64,
                                           wv, bv + l * 64, ws, bs + l * 64,
                                           pq, pk, pv, ps, n);
        clear_layer_kernel<<<divup((long long)n * 64, 256), 256>>>(n);
        edge_pass1_kernel<<<divup((long long)e * 4, 256), 256>>>(ei, eattr, we, be + l * 64, e);
        edge_pass2_kernel<<<divup((long long)e * 4, 256), 256>>>(ei, eattr, we, be + l * 64, e);
        finalize_attn_kernel<<<divup((long long)n * 4, 256), 256>>>(n);
        bn_stats_kernel<<<2048, 256>>>(n);
        bn_apply_kernel<<<divup((long long)n * 16, 256), 256>>>(gamma + l * 64, beta + l * 64, n);
    }

    clear_pool_kernel<<<divup((long long)G * 64, 256), 256>>>(G);
    pool_kernel<<<divup((long long)n * 16, 256), 256>>>(batch, n);
    reg_kernel<<<G, 128>>>(rw1, rb1, rw2, rb2, out);
}